// round 16
// baseline (speedup 1.0000x reference)
#include <cuda_runtime.h>
#include <math.h>

// Problem constants
#define W_DIM   512
#define IN_CH   512
#define OUT_CH  3
#define BATCH   32
#define HW      16384          // 128*128 pixels per (b, channel) plane
#define HW4     4096           // pixels / 4 (float4 granularity)
#define CLAMP_V 256.0f

#define TB      128            // threads per block
#define SW_N    (OUT_CH * IN_CH)      // 1536
#define WK_PER_T (SW_N / TB)          // 12
#define PRE     8               // x channel-steps prefetched before the wait

#define NS_BLOCKS 512           // styles blocks (bids 0..511, dispatched first)
#define NT_BLOCKS 1024          // torgb blocks  (bids 512..1535)
#define OCT_BLOCKS (NS_BLOCKS / 4)   // 128 styles blocks per batch octet

// Scratch for per-(batch, channel) styles. 32*512 floats = 64 KB.
__device__ float g_styles[BATCH * IN_CH];
__device__ int   g_done[4];     // styles blocks completed, per batch octet
__device__ int   g_tdone;       // torgb blocks completed (reset each call)

__device__ __forceinline__ float clampf(float v) {
    return fminf(fmaxf(v, -CLAMP_V), CLAMP_V);
}

// ---------------------------------------------------------------------------
// Fused kernel. Blocks [0, NS_BLOCKS): styles producers, grouped so that
// bids [q*128, (q+1)*128) cover batch octet q (batches q*8..q*8+7) for all
// 512 channels. Blocks [NS_BLOCKS, ...): torgb consumers; each waits only
// on its own batch octet's counter -> staggered release instead of a
// global barrier over all styles work.
// ---------------------------------------------------------------------------
__global__ void __launch_bounds__(TB) fused_kernel(
    const float* __restrict__ x,     // (32, 512, 128, 128)
    const float* __restrict__ w,     // (32, 512)
    const float* __restrict__ aw,    // (512, 512)
    const float* __restrict__ ab,    // (512,)
    const float* __restrict__ wk,    // (3, 512)
    const float* __restrict__ bias,  // (3,)
    float*       __restrict__ out)   // (32, 3, 128, 128)
{
    __shared__ float sw[SW_N];   // 6 KB (torgb blocks only)

    const int bid = blockIdx.x;
    const int tid = threadIdx.x;

    if (bid < NS_BLOCKS) {
        // ================= styles producer =================
        // gw in [0, 2048): octet q = gw >> 9, channel i = gw & 511.
        // Block bids [q*128, (q+1)*128) all belong to octet q.
        const int gw   = bid * (TB / 32) + (tid >> 5);
        const int lane = tid & 31;
        const int q = gw >> 9;             // batch octet 0..3
        const int i = gw & (IN_CH - 1);    // channel 0..511

        const float4* aw4 = (const float4*)(aw + (size_t)i * W_DIM);
        float4 av[4];
#pragma unroll
        for (int c = 0; c < 4; c++) av[c] = aw4[c * 32 + lane];

        const float fc_gain     = 1.0f / sqrtf((float)W_DIM);
        const float weight_gain = 1.0f / sqrtf((float)IN_CH);
        const float abi = ab[i];

#pragma unroll
        for (int bb = 0; bb < 8; bb++) {
            const int b = q * 8 + bb;
            const float4* w4 = (const float4*)(w + (size_t)b * W_DIM);
            float p = 0.0f;
#pragma unroll
            for (int c = 0; c < 4; c++) {
                float4 wv = w4[c * 32 + lane];
                p += av[c].x * wv.x + av[c].y * wv.y + av[c].z * wv.z + av[c].w * wv.w;
            }
#pragma unroll
            for (int off = 16; off; off >>= 1)
                p += __shfl_xor_sync(0xffffffffu, p, off);
            if (lane == 0)
                g_styles[b * IN_CH + i] = (p * fc_gain + abi) * weight_gain;
        }

        __syncthreads();
        if (tid == 0) {
            __threadfence();                 // publish g_styles before flag
            atomicAdd(&g_done[q], 1);
        }
        return;
    }

    // ================= torgb consumer =================
    const int t  = bid - NS_BLOCKS;          // 0..1023
    const int b  = t >> 5;                   // batch 0..31
    const int ch = t & 31;                   // pixel chunk 0..31
    const int p  = ch * TB + tid;            // 0..4095 float4 index
    const int oct = b >> 3;                  // batch octet 0..3

    const float4* xb = (const float4*)x + (size_t)b * IN_CH * HW4 + p;
    const float* st = g_styles + (size_t)b * IN_CH;

    // --- prologue independent of styles: loads fly during the wait ---
    const float b0 = bias[0], b1 = bias[1], b2 = bias[2];
    float wkr[WK_PER_T];
#pragma unroll
    for (int k = 0; k < WK_PER_T; k++)
        wkr[k] = wk[k * TB + tid];

    float4 xpre[PRE];
#pragma unroll
    for (int k = 0; k < PRE; k++)
        xpre[k] = __ldcs(xb + (size_t)k * HW4);

    // Wait only for this batch octet's styles blocks.
    if (tid == 0) {
        volatile int* f = &g_done[oct];
        while (*f != OCT_BLOCKS) { }
    }
    __syncthreads();

#pragma unroll
    for (int k = 0; k < WK_PER_T; k++) {
        int idx = k * TB + tid;
        sw[idx] = wkr[k] * __ldcg(st + (idx & (IN_CH - 1)));
    }
    __syncthreads();

    float4 a0 = {0.f, 0.f, 0.f, 0.f};
    float4 a1 = a0;
    float4 a2 = a0;

#pragma unroll
    for (int i = 0; i < PRE; i++) {
        float4 xv = xpre[i];
        float s0 = sw[i], s1 = sw[IN_CH + i], s2 = sw[2 * IN_CH + i];
        a0.x = fmaf(s0, xv.x, a0.x); a0.y = fmaf(s0, xv.y, a0.y);
        a0.z = fmaf(s0, xv.z, a0.z); a0.w = fmaf(s0, xv.w, a0.w);
        a1.x = fmaf(s1, xv.x, a1.x); a1.y = fmaf(s1, xv.y, a1.y);
        a1.z = fmaf(s1, xv.z, a1.z); a1.w = fmaf(s1, xv.w, a1.w);
        a2.x = fmaf(s2, xv.x, a2.x); a2.y = fmaf(s2, xv.y, a2.y);
        a2.z = fmaf(s2, xv.z, a2.z); a2.w = fmaf(s2, xv.w, a2.w);
    }

#pragma unroll 8
    for (int i = PRE; i < IN_CH; i++) {
        float4 xv = __ldcs(xb + (size_t)i * HW4);
        float s0 = sw[i], s1 = sw[IN_CH + i], s2 = sw[2 * IN_CH + i];
        a0.x = fmaf(s0, xv.x, a0.x); a0.y = fmaf(s0, xv.y, a0.y);
        a0.z = fmaf(s0, xv.z, a0.z); a0.w = fmaf(s0, xv.w, a0.w);
        a1.x = fmaf(s1, xv.x, a1.x); a1.y = fmaf(s1, xv.y, a1.y);
        a1.z = fmaf(s1, xv.z, a1.z); a1.w = fmaf(s1, xv.w, a1.w);
        a2.x = fmaf(s2, xv.x, a2.x); a2.y = fmaf(s2, xv.y, a2.y);
        a2.z = fmaf(s2, xv.z, a2.z); a2.w = fmaf(s2, xv.w, a2.w);
    }

    float4 r0, r1, r2;
    r0.x = clampf(a0.x + b0); r0.y = clampf(a0.y + b0);
    r0.z = clampf(a0.z + b0); r0.w = clampf(a0.w + b0);
    r1.x = clampf(a1.x + b1); r1.y = clampf(a1.y + b1);
    r1.z = clampf(a1.z + b1); r1.w = clampf(a1.w + b1);
    r2.x = clampf(a2.x + b2); r2.y = clampf(a2.y + b2);
    r2.z = clampf(a2.z + b2); r2.w = clampf(a2.w + b2);

    float4* ob = (float4*)out + (size_t)b * OUT_CH * HW4 + p;
    __stcs(ob,           r0);
    __stcs(ob + HW4,     r1);
    __stcs(ob + 2 * HW4, r2);

    // Replay-safe counter reset: the last torgb block zeroes everything.
    if (tid == 0) {
        int v = atomicAdd(&g_tdone, 1);
        if (v == NT_BLOCKS - 1) {
            g_done[0] = 0; g_done[1] = 0; g_done[2] = 0; g_done[3] = 0;
            g_tdone = 0;
            __threadfence();
        }
    }
}

// ---------------------------------------------------------------------------
// kernel_launch
// Input order (metadata): x, w, affine_weight, affine_bias, weight, bias
// ---------------------------------------------------------------------------
extern "C" void kernel_launch(void* const* d_in, const int* in_sizes, int n_in,
                              void* d_out, int out_size)
{
    const float* x    = (const float*)d_in[0];
    const float* w    = (const float*)d_in[1];
    const float* aw   = (const float*)d_in[2];
    const float* ab   = (const float*)d_in[3];
    const float* wk   = (const float*)d_in[4];
    const float* bias = (const float*)d_in[5];
    float* out = (float*)d_out;

    fused_kernel<<<NS_BLOCKS + NT_BLOCKS, TB>>>(x, w, aw, ab, wk, bias, out);
}

// round 17
// speedup vs baseline: 1.2285x; 1.2285x over previous
#include <cuda_runtime.h>
#include <math.h>

// Problem constants
#define W_DIM   512
#define IN_CH   512
#define OUT_CH  3
#define BATCH   32
#define HW      16384          // 128*128 pixels per (b, channel) plane
#define HW4     4096           // pixels / 4 (float4 granularity)
#define CLAMP_V 256.0f

#define TB      128            // threads per block
#define SW_N    (OUT_CH * IN_CH)      // 1536
#define WK_PER_T (SW_N / TB)          // 12
#define PRE     4               // x channel-steps prefetched before the wait
                                // (PRE=8 proven harmful: regs 74 -> occ 32% -> 197us)

#define NS_BLOCKS 512           // styles blocks (bids 0..511, dispatched first)
#define NT_BLOCKS 1024          // torgb blocks  (bids 512..1535)
#define OCT_BLOCKS (NS_BLOCKS / 4)   // 128 styles blocks per batch octet

// Scratch for per-(batch, channel) styles. 32*512 floats = 64 KB.
__device__ float g_styles[BATCH * IN_CH];
__device__ int   g_done[4];     // styles blocks completed, per batch octet
__device__ int   g_tdone;       // torgb blocks completed (reset each call)

__device__ __forceinline__ float clampf(float v) {
    return fminf(fmaxf(v, -CLAMP_V), CLAMP_V);
}

// ---------------------------------------------------------------------------
// Fused kernel. Blocks [0, NS_BLOCKS): styles producers, grouped so that
// bids [q*128, (q+1)*128) cover batch octet q (batches q*8..q*8+7) for all
// 512 channels. Blocks [NS_BLOCKS, ...): torgb consumers; each waits only
// on its own batch octet's counter -> staggered release.
// Styles blocks carry the lowest bids -> dispatched in wave 1 ahead of all
// torgb blocks, so the spin-wait can never starve them.
// ---------------------------------------------------------------------------
__global__ void __launch_bounds__(TB) fused_kernel(
    const float* __restrict__ x,     // (32, 512, 128, 128)
    const float* __restrict__ w,     // (32, 512)
    const float* __restrict__ aw,    // (512, 512)
    const float* __restrict__ ab,    // (512,)
    const float* __restrict__ wk,    // (3, 512)
    const float* __restrict__ bias,  // (3,)
    float*       __restrict__ out)   // (32, 3, 128, 128)
{
    __shared__ float sw[SW_N];   // 6 KB (torgb blocks only)

    const int bid = blockIdx.x;
    const int tid = threadIdx.x;

    if (bid < NS_BLOCKS) {
        // ================= styles producer =================
        // gw in [0, 2048): octet q = gw >> 9, channel i = gw & 511.
        const int gw   = bid * (TB / 32) + (tid >> 5);
        const int lane = tid & 31;
        const int q = gw >> 9;             // batch octet 0..3
        const int i = gw & (IN_CH - 1);    // channel 0..511

        const float4* aw4 = (const float4*)(aw + (size_t)i * W_DIM);
        float4 av[4];
#pragma unroll
        for (int c = 0; c < 4; c++) av[c] = aw4[c * 32 + lane];

        const float fc_gain     = 1.0f / sqrtf((float)W_DIM);
        const float weight_gain = 1.0f / sqrtf((float)IN_CH);
        const float abi = ab[i];

#pragma unroll
        for (int bb = 0; bb < 8; bb++) {
            const int b = q * 8 + bb;
            const float4* w4 = (const float4*)(w + (size_t)b * W_DIM);
            float p = 0.0f;
#pragma unroll
            for (int c = 0; c < 4; c++) {
                float4 wv = w4[c * 32 + lane];
                p += av[c].x * wv.x + av[c].y * wv.y + av[c].z * wv.z + av[c].w * wv.w;
            }
#pragma unroll
            for (int off = 16; off; off >>= 1)
                p += __shfl_xor_sync(0xffffffffu, p, off);
            if (lane == 0)
                g_styles[b * IN_CH + i] = (p * fc_gain + abi) * weight_gain;
        }

        __syncthreads();
        if (tid == 0) {
            __threadfence();                 // publish g_styles before flag
            atomicAdd(&g_done[q], 1);
        }
        return;
    }

    // ================= torgb consumer =================
    const int t  = bid - NS_BLOCKS;          // 0..1023
    const int b  = t >> 5;                   // batch 0..31
    const int ch = t & 31;                   // pixel chunk 0..31
    const int p  = ch * TB + tid;            // 0..4095 float4 index
    const int oct = b >> 3;                  // batch octet 0..3

    const float4* xb = (const float4*)x + (size_t)b * IN_CH * HW4 + p;
    const float* st = g_styles + (size_t)b * IN_CH;

    // --- prologue independent of styles: loads fly during the wait ---
    const float b0 = bias[0], b1 = bias[1], b2 = bias[2];
    float wkr[WK_PER_T];
#pragma unroll
    for (int k = 0; k < WK_PER_T; k++)
        wkr[k] = wk[k * TB + tid];

    float4 xpre[PRE];
#pragma unroll
    for (int k = 0; k < PRE; k++)
        xpre[k] = __ldcs(xb + (size_t)k * HW4);

    // Wait only for this batch octet's styles blocks.
    if (tid == 0) {
        volatile int* f = &g_done[oct];
        while (*f != OCT_BLOCKS) { }
    }
    __syncthreads();

#pragma unroll
    for (int k = 0; k < WK_PER_T; k++) {
        int idx = k * TB + tid;
        sw[idx] = wkr[k] * __ldcg(st + (idx & (IN_CH - 1)));
    }
    __syncthreads();

    float4 a0 = {0.f, 0.f, 0.f, 0.f};
    float4 a1 = a0;
    float4 a2 = a0;

#pragma unroll
    for (int i = 0; i < PRE; i++) {
        float4 xv = xpre[i];
        float s0 = sw[i], s1 = sw[IN_CH + i], s2 = sw[2 * IN_CH + i];
        a0.x = fmaf(s0, xv.x, a0.x); a0.y = fmaf(s0, xv.y, a0.y);
        a0.z = fmaf(s0, xv.z, a0.z); a0.w = fmaf(s0, xv.w, a0.w);
        a1.x = fmaf(s1, xv.x, a1.x); a1.y = fmaf(s1, xv.y, a1.y);
        a1.z = fmaf(s1, xv.z, a1.z); a1.w = fmaf(s1, xv.w, a1.w);
        a2.x = fmaf(s2, xv.x, a2.x); a2.y = fmaf(s2, xv.y, a2.y);
        a2.z = fmaf(s2, xv.z, a2.z); a2.w = fmaf(s2, xv.w, a2.w);
    }

#pragma unroll 8
    for (int i = PRE; i < IN_CH; i++) {
        float4 xv = __ldcs(xb + (size_t)i * HW4);
        float s0 = sw[i], s1 = sw[IN_CH + i], s2 = sw[2 * IN_CH + i];
        a0.x = fmaf(s0, xv.x, a0.x); a0.y = fmaf(s0, xv.y, a0.y);
        a0.z = fmaf(s0, xv.z, a0.z); a0.w = fmaf(s0, xv.w, a0.w);
        a1.x = fmaf(s1, xv.x, a1.x); a1.y = fmaf(s1, xv.y, a1.y);
        a1.z = fmaf(s1, xv.z, a1.z); a1.w = fmaf(s1, xv.w, a1.w);
        a2.x = fmaf(s2, xv.x, a2.x); a2.y = fmaf(s2, xv.y, a2.y);
        a2.z = fmaf(s2, xv.z, a2.z); a2.w = fmaf(s2, xv.w, a2.w);
    }

    float4 r0, r1, r2;
    r0.x = clampf(a0.x + b0); r0.y = clampf(a0.y + b0);
    r0.z = clampf(a0.z + b0); r0.w = clampf(a0.w + b0);
    r1.x = clampf(a1.x + b1); r1.y = clampf(a1.y + b1);
    r1.z = clampf(a1.z + b1); r1.w = clampf(a1.w + b1);
    r2.x = clampf(a2.x + b2); r2.y = clampf(a2.y + b2);
    r2.z = clampf(a2.z + b2); r2.w = clampf(a2.w + b2);

    float4* ob = (float4*)out + (size_t)b * OUT_CH * HW4 + p;
    __stcs(ob,           r0);
    __stcs(ob + HW4,     r1);
    __stcs(ob + 2 * HW4, r2);

    // Replay-safe counter reset: the last torgb block zeroes everything.
    if (tid == 0) {
        int v = atomicAdd(&g_tdone, 1);
        if (v == NT_BLOCKS - 1) {
            g_done[0] = 0; g_done[1] = 0; g_done[2] = 0; g_done[3] = 0;
            g_tdone = 0;
            __threadfence();
        }
    }
}

// ---------------------------------------------------------------------------
// kernel_launch
// Input order (metadata): x, w, affine_weight, affine_bias, weight, bias
// ---------------------------------------------------------------------------
extern "C" void kernel_launch(void* const* d_in, const int* in_sizes, int n_in,
                              void* d_out, int out_size)
{
    const float* x    = (const float*)d_in[0];
    const float* w    = (const float*)d_in[1];
    const float* aw   = (const float*)d_in[2];
    const float* ab   = (const float*)d_in[3];
    const float* wk   = (const float*)d_in[4];
    const float* bias = (const float*)d_in[5];
    float* out = (float*)d_out;

    fused_kernel<<<NS_BLOCKS + NT_BLOCKS, TB>>>(x, w, aw, ab, wk, bias, out);
}